// round 7
// baseline (speedup 1.0000x reference)
#include <cuda_runtime.h>
#include <math.h>
#include <stdint.h>

typedef unsigned long long ull;

// ---------------------------------------------------------------------------
// helpers
// ---------------------------------------------------------------------------
__device__ __forceinline__ void ffma2(ull& d, ull a, ull b) {
    asm("fma.rn.f32x2 %0, %1, %2, %0;" : "+l"(d) : "l"(a), "l"(b));
}
__device__ __forceinline__ ull add2(ull a, ull b) {
    ull r; asm("add.rn.f32x2 %0, %1, %2;" : "=l"(r) : "l"(a), "l"(b)); return r;
}
__device__ __forceinline__ ull mul2(ull a, ull b) {
    ull r; asm("mul.rn.f32x2 %0, %1, %2;" : "=l"(r) : "l"(a), "l"(b)); return r;
}
__device__ __forceinline__ ull dup2(float x) {
    ull r; asm("mov.b64 %0, {%1, %1};" : "=l"(r) : "f"(x)); return r;
}
__device__ __forceinline__ float2 unpk(ull v) {
    float2 r; asm("mov.b64 {%0, %1}, %2;" : "=f"(r.x), "=f"(r.y) : "l"(v)); return r;
}
__device__ __forceinline__ uint32_t f2tf32(float x) {
    uint32_t u; asm("cvt.rna.tf32.f32 %0, %1;" : "=r"(u) : "f"(x)); return u;
}
__device__ __forceinline__ void mma_tf32(float* c, const uint32_t* a, const uint32_t* b) {
    asm volatile(
        "mma.sync.aligned.m16n8k8.row.col.f32.tf32.tf32.f32 "
        "{%0,%1,%2,%3}, {%4,%5,%6,%7}, {%8,%9}, {%0,%1,%2,%3};"
        : "+f"(c[0]), "+f"(c[1]), "+f"(c[2]), "+f"(c[3])
        : "r"(a[0]), "r"(a[1]), "r"(a[2]), "r"(a[3]), "r"(b[0]), "r"(b[1]));
}

#define TOK 4096
#define CD 768
#define FD 3072

__device__ float g_x[TOK * CD];
__device__ float g_xn[TOK * CD];
__device__ float g_qkv[TOK * 3 * CD];
__device__ float g_attn[TOK * CD];
__device__ float g_h[TOK * FD];
__device__ float g_t1[TOK * 256];
__device__ float g_t2[TOK * 256];
__device__ float g_bh[12 * TOK * 64];
__device__ float g_bw[12 * TOK * 64];

// ---------------------------------------------------------------------------
// LayerNorm 768
// ---------------------------------------------------------------------------
__global__ __launch_bounds__(256) void ln768_kernel(
    const float* __restrict__ in, const float* __restrict__ g,
    const float* __restrict__ b, float* __restrict__ out, float eps)
{
    int row = blockIdx.x;
    int t = threadIdx.x;
    const float* xp = in + (size_t)row * CD;
    float v0 = xp[t], v1 = xp[t + 256], v2 = xp[t + 512];
    __shared__ float red[256];
    red[t] = v0 + v1 + v2;
    __syncthreads();
#pragma unroll
    for (int off = 128; off > 0; off >>= 1) {
        if (t < off) red[t] += red[t + off];
        __syncthreads();
    }
    float mean = red[0] * (1.0f / 768.0f);
    __syncthreads();
    float d0 = v0 - mean, d1 = v1 - mean, d2 = v2 - mean;
    red[t] = d0 * d0 + d1 * d1 + d2 * d2;
    __syncthreads();
#pragma unroll
    for (int off = 128; off > 0; off >>= 1) {
        if (t < off) red[t] += red[t + off];
        __syncthreads();
    }
    float inv = rsqrtf(red[0] * (1.0f / 768.0f) + eps);
    float* op = out + (size_t)row * CD;
    op[t]       = d0 * inv * g[t]       + b[t];
    op[t + 256] = d1 * inv * g[t + 256] + b[t + 256];
    op[t + 512] = d2 * inv * g[t + 512] + b[t + 512];
}

// ---------------------------------------------------------------------------
// LayerNorm 256 (neck), optional NCHW transpose on write
// ---------------------------------------------------------------------------
__global__ __launch_bounds__(256) void ln256_kernel(
    const float* __restrict__ in, const float* __restrict__ g,
    const float* __restrict__ b, float* __restrict__ out, float eps, int transpose)
{
    int p = blockIdx.x;
    int c = threadIdx.x;
    float v = in[(size_t)p * 256 + c];
    __shared__ float red[256];
    red[c] = v;
    __syncthreads();
#pragma unroll
    for (int off = 128; off > 0; off >>= 1) {
        if (c < off) red[c] += red[c + off];
        __syncthreads();
    }
    float mean = red[0] * (1.0f / 256.0f);
    __syncthreads();
    float d = v - mean;
    red[c] = d * d;
    __syncthreads();
#pragma unroll
    for (int off = 128; off > 0; off >>= 1) {
        if (c < off) red[c] += red[c + off];
        __syncthreads();
    }
    float inv = rsqrtf(red[0] * (1.0f / 256.0f) + eps);
    float r = d * inv * g[c] + b[c];
    if (transpose)
        out[(size_t)c * TOK + p] = r;
    else
        out[(size_t)p * 256 + c] = r;
}

// ---------------------------------------------------------------------------
// GEMM v3: tensor-core tf32 (3xTF32 for fp32-like accuracy).
// C[M,N] = A[M,K] @ B[K,N] (+bias,+gelu,+residual)
// Block tile 128x128x32, 8 warps (2x4), warp tile 64x32, mma m16n8k8.
// Smem: Ahi/Alo [128][32] swizzle k^((m&7)<<2); Bhi/Blo [32][128] swizzle
// n^((k&7)<<3). All frag loads and float4 stores bank-conflict-free.
// Requires M%128==0, N%128==0, K%32==0.
// ---------------------------------------------------------------------------
#define G3_SMEM (16384 * 4)

template<bool GELU, bool HASBIAS, bool HASRES>
__global__ __launch_bounds__(256, 1) void gemm3_kernel(
    const float* __restrict__ A, const float* __restrict__ Bm,
    const float* __restrict__ bias, const float* __restrict__ res,
    float* __restrict__ Cm, int M, int N, int K)
{
    extern __shared__ float sm[];
    float* Ahi = sm;            // 4096
    float* Alo = sm + 4096;
    float* Bhi = sm + 8192;     // 4096
    float* Blo = sm + 12288;

    const int tid = threadIdx.x;
    const int lane = tid & 31;
    const int warp = tid >> 5;
    const int wm = (warp >> 2) * 64;   // 0 or 64
    const int wn = (warp & 3) * 32;    // 0,32,64,96
    const int r = lane >> 2;           // 0..7
    const int cc = lane & 3;           // 0..3
    const int row0 = blockIdx.y * 128, col0 = blockIdx.x * 128;

    float acc[4][4][4];
#pragma unroll
    for (int mi = 0; mi < 4; mi++)
#pragma unroll
        for (int ni = 0; ni < 4; ni++)
#pragma unroll
            for (int j = 0; j < 4; j++) acc[mi][ni][j] = 0.0f;

    const int am = tid >> 3;           // 0..31 (+32*i)
    const int ak4 = (tid & 7) * 4;
    const int bk = tid >> 5;           // 0..7 (+8*i)
    const int bn4 = (tid & 31) * 4;

    float4 apf[4], bpf[4];

#define LOADG(T) do { \
        int k0 = (T) * 32; \
        _Pragma("unroll") \
        for (int i = 0; i < 4; i++) { \
            apf[i] = *reinterpret_cast<const float4*>( \
                A + (size_t)(row0 + am + 32 * i) * K + k0 + ak4); \
            bpf[i] = *reinterpret_cast<const float4*>( \
                Bm + (size_t)(k0 + bk + 8 * i) * N + col0 + bn4); \
        } \
    } while (0)

#define SPLIT4(v, h4, l4) do { \
        uint32_t hx = f2tf32(v.x), hy = f2tf32(v.y), hz = f2tf32(v.z), hw = f2tf32(v.w); \
        h4 = make_float4(__uint_as_float(hx), __uint_as_float(hy), \
                         __uint_as_float(hz), __uint_as_float(hw)); \
        l4 = make_float4( \
            __uint_as_float(f2tf32(v.x - h4.x)), __uint_as_float(f2tf32(v.y - h4.y)), \
            __uint_as_float(f2tf32(v.z - h4.z)), __uint_as_float(f2tf32(v.w - h4.w))); \
    } while (0)

#define STORES() do { \
        _Pragma("unroll") \
        for (int i = 0; i < 4; i++) { \
            int m = am + 32 * i; \
            int kk = ak4 ^ ((m & 7) << 2); \
            float4 h4, l4; \
            SPLIT4(apf[i], h4, l4); \
            *reinterpret_cast<float4*>(Ahi + m * 32 + kk) = h4; \
            *reinterpret_cast<float4*>(Alo + m * 32 + kk) = l4; \
            int k = bk + 8 * i; \
            int nn = bn4 ^ ((k & 7) << 3); \
            SPLIT4(bpf[i], h4, l4); \
            *reinterpret_cast<float4*>(Bhi + k * 128 + nn) = h4; \
            *reinterpret_cast<float4*>(Blo + k * 128 + nn) = l4; \
        } \
    } while (0)

    const int NT = K >> 5;
    LOADG(0);

    for (int t = 0; t < NT; t++) {
        STORES();
        __syncthreads();
        if (t + 1 < NT) LOADG(t + 1);

#pragma unroll
        for (int ks = 0; ks < 4; ks++) {
            uint32_t ah[4][4], al[4][4], bh[4][2], bl[4][2];
#pragma unroll
            for (int mi = 0; mi < 4; mi++) {
                int m0 = wm + mi * 16 + r;
                int sw = (m0 & 7) << 2;            // (m0+8)&7 == m0&7
                int kA0 = (ks * 8 + cc) ^ sw;
                int kA1 = (ks * 8 + cc + 4) ^ sw;
                ah[mi][0] = __float_as_uint(Ahi[m0 * 32 + kA0]);
                ah[mi][1] = __float_as_uint(Ahi[(m0 + 8) * 32 + kA0]);
                ah[mi][2] = __float_as_uint(Ahi[m0 * 32 + kA1]);
                ah[mi][3] = __float_as_uint(Ahi[(m0 + 8) * 32 + kA1]);
                al[mi][0] = __float_as_uint(Alo[m0 * 32 + kA0]);
                al[mi][1] = __float_as_uint(Alo[(m0 + 8) * 32 + kA0]);
                al[mi][2] = __float_as_uint(Alo[m0 * 32 + kA1]);
                al[mi][3] = __float_as_uint(Alo[(m0 + 8) * 32 + kA1]);
            }
#pragma unroll
            for (int ni = 0; ni < 4; ni++) {
                int n0 = wn + ni * 8 + r;
                int kB0 = ks * 8 + cc;
                int kB1 = ks * 8 + cc + 4;
                int nB0 = n0 ^ ((kB0 & 7) << 3);
                int nB1 = n0 ^ ((kB1 & 7) << 3);
                bh[ni][0] = __float_as_uint(Bhi[kB0 * 128 + nB0]);
                bh[ni][1] = __float_as_uint(Bhi[kB1 * 128 + nB1]);
                bl[ni][0] = __float_as_uint(Blo[kB0 * 128 + nB0]);
                bl[ni][1] = __float_as_uint(Blo[kB1 * 128 + nB1]);
            }
#pragma unroll
            for (int mi = 0; mi < 4; mi++)
#pragma unroll
                for (int ni = 0; ni < 4; ni++) {
                    mma_tf32(acc[mi][ni], ah[mi], bh[ni]);
                    mma_tf32(acc[mi][ni], al[mi], bh[ni]);
                    mma_tf32(acc[mi][ni], ah[mi], bl[ni]);
                }
        }
        __syncthreads();
    }
#undef LOADG
#undef SPLIT4
#undef STORES

    // epilogue: c0,c1 -> (row, 2c),(row, 2c+1); c2,c3 -> row+8
#pragma unroll
    for (int mi = 0; mi < 4; mi++) {
#pragma unroll
        for (int half = 0; half < 2; half++) {
            int grow = row0 + wm + mi * 16 + r + half * 8;
#pragma unroll
            for (int ni = 0; ni < 4; ni++) {
                int gcol = col0 + wn + ni * 8 + 2 * cc;
                float v0 = acc[mi][ni][half * 2 + 0];
                float v1 = acc[mi][ni][half * 2 + 1];
                if (HASBIAS) { v0 += bias[gcol]; v1 += bias[gcol + 1]; }
                if (GELU) {
                    v0 = 0.5f * v0 * (1.0f + erff(v0 * 0.70710678118654752f));
                    v1 = 0.5f * v1 * (1.0f + erff(v1 * 0.70710678118654752f));
                }
                size_t o = (size_t)grow * N + gcol;
                if (HASRES) {
                    float2 rr = *reinterpret_cast<const float2*>(res + o);
                    v0 += rr.x; v1 += rr.y;
                }
                *reinterpret_cast<float2*>(Cm + o) = make_float2(v0, v1);
            }
        }
    }
}

// ---------------------------------------------------------------------------
// Rel-pos bias precompute (global attention block)
// ---------------------------------------------------------------------------
__global__ __launch_bounds__(64) void relbias_kernel(
    const float* __restrict__ qkv, const float* __restrict__ relH,
    const float* __restrict__ relW, float* __restrict__ bh, float* __restrict__ bw)
{
    int q = blockIdx.x, n = blockIdx.y, j = threadIdx.x;
    __shared__ float qs[64];
    qs[j] = qkv[(size_t)q * 2304 + n * 64 + j];
    __syncthreads();
    int qh = q >> 6, qw = q & 63;
    const float* th = relH + (qh - j + 63) * 64;
    const float* tw = relW + (qw - j + 63) * 64;
    float a = 0.f, b = 0.f;
#pragma unroll 8
    for (int d = 0; d < 64; d++) {
        a = fmaf(qs[d], th[d], a);
        b = fmaf(qs[d], tw[d], b);
    }
    size_t o = ((size_t)n * TOK + q) * 64 + j;
    bh[o] = a;
    bw[o] = b;
}

// ---------------------------------------------------------------------------
// Global attention: 128 queries/block, f32x2 math, bias tables in smem.
// ---------------------------------------------------------------------------
#define GA2_SMEM ((128 * 65 * 2 + 64 * 64 * 2) * 4)

__global__ __launch_bounds__(128) void glob_attn2_kernel(
    const float* __restrict__ qkv, const float* __restrict__ bh,
    const float* __restrict__ bw, float* __restrict__ out)
{
    extern __shared__ float sm[];
    float* rh_s = sm;
    float* rw_s = sm + 128 * 65;
    float* Ks   = sm + 2 * 128 * 65;
    float* Vs   = Ks + 64 * 64;
    const int n = blockIdx.y, tid = threadIdx.x;
    const int q0 = blockIdx.x * 128;

    for (int idx = tid; idx < 128 * 64; idx += 128) {
        int qq = idx >> 6, j = idx & 63;
        size_t g = ((size_t)n * TOK + q0 + qq) * 64 + j;
        rh_s[qq * 65 + j] = bh[g];
        rw_s[qq * 65 + j] = bw[g];
    }

    ull q2[32], o2[32];
    const float* qp = qkv + (size_t)(q0 + tid) * 2304 + n * 64;
#pragma unroll
    for (int i = 0; i < 32; i++) {
        q2[i] = *reinterpret_cast<const ull*>(qp + 2 * i);
        o2[i] = 0ULL;
    }
    float m = -1e30f, l = 0.0f;

    for (int kt = 0; kt < 64; kt++) {
        __syncthreads();
#pragma unroll
        for (int i = 0; i < 8; i++) {
            int idx = tid + i * 128;
            int row = idx >> 4, c4 = (idx & 15) * 4;
            const float* kb = qkv + (size_t)(kt * 64 + row) * 2304 + 768 + n * 64 + c4;
            *reinterpret_cast<float4*>(&Ks[row * 64 + c4]) = *reinterpret_cast<const float4*>(kb);
            *reinterpret_cast<float4*>(&Vs[row * 64 + c4]) = *reinterpret_cast<const float4*>(kb + 768);
        }
        __syncthreads();
        float rhv = rh_s[tid * 65 + kt];
        for (int kk = 0; kk < 64; kk++) {
            const ull* kp = reinterpret_cast<const ull*>(Ks + kk * 64);
            ull s0 = 0, s1 = 0, s2 = 0, s3 = 0;
#pragma unroll
            for (int d = 0; d < 32; d += 4) {
                ffma2(s0, q2[d],     kp[d]);
                ffma2(s1, q2[d + 1], kp[d + 1]);
                ffma2(s2, q2[d + 2], kp[d + 2]);
                ffma2(s3, q2[d + 3], kp[d + 3]);
            }
            s0 = add2(s0, s1); s2 = add2(s2, s3); s0 = add2(s0, s2);
            float2 sp = unpk(s0);
            float s = fmaf(sp.x + sp.y, 0.125f, rhv + rw_s[tid * 65 + kk]);
            float p;
            if (s > m) {
                float corr = __expf(m - s);
                l *= corr;
                ull c2 = dup2(corr);
#pragma unroll
                for (int d = 0; d < 32; d++) o2[d] = mul2(o2[d], c2);
                m = s;
                p = 1.0f;
            } else {
                p = __expf(s - m);
            }
            l += p;
            ull p2 = dup2(p);
            const ull* vp = reinterpret_cast<const ull*>(Vs + kk * 64);
#pragma unroll
            for (int d = 0; d < 32; d++) ffma2(o2[d], p2, vp[d]);
        }
    }
    ull iv = dup2(1.0f / l);
    float* op = out + (size_t)(q0 + tid) * CD + n * 64;
#pragma unroll
    for (int d = 0; d < 32; d++)
        *reinterpret_cast<ull*>(op + 2 * d) = mul2(o2[d], iv);
}

// ---------------------------------------------------------------------------
// Windowed attention (ws=14): f32x2 math, per-thread bias rows in smem.
// ---------------------------------------------------------------------------
#define WIN2_SMEM ((196 * 64 * 2 + 2 * 14 * 256) * 4)

__global__ __launch_bounds__(256) void win_attn2_kernel(
    const float* __restrict__ qkv, const float* __restrict__ qkv_b,
    const float* __restrict__ relH, const float* __restrict__ relW,
    float* __restrict__ out)
{
    extern __shared__ float sm[];
    float* Ks = sm;
    float* Vs = sm + 196 * 64;
    float* rh_s = sm + 2 * 196 * 64;
    float* rw_s = rh_s + 14 * 256;
    const int win = blockIdx.x, n = blockIdx.y;
    const int wh = (win / 5) * 14, ww = (win % 5) * 14;
    const int tid = threadIdx.x;

    for (int idx = tid; idx < 196 * 64; idx += 256) {
        int r = idx >> 6, d = idx & 63;
        int gh = wh + r / 14, gw = ww + r % 14;
        float kk, vv;
        if (gh < 64 && gw < 64) {
            size_t base = (size_t)(gh * 64 + gw) * 2304 + n * 64 + d;
            kk = qkv[base + 768];
            vv = qkv[base + 1536];
        } else {
            kk = qkv_b[768 + n * 64 + d];
            vv = qkv_b[1536 + n * 64 + d];
        }
        Ks[idx] = kk;
        Vs[idx] = vv;
    }
    __syncthreads();

    if (tid >= 196) return;
    const int qh = tid / 14, qw = tid % 14;
    const int gh = wh + qh, gw = ww + qw;
    if (gh >= 64 || gw >= 64) return;
    const int tok = gh * 64 + gw;

    ull q2[32];
    const float* qp = qkv + (size_t)tok * 2304 + n * 64;
#pragma unroll
    for (int i = 0; i < 32; i++) q2[i] = *reinterpret_cast<const ull*>(qp + 2 * i);

#pragma unroll 2
    for (int j = 0; j < 14; j++) {
        const ull* th = reinterpret_cast<const ull*>(relH + (qh - j + 13) * 64);
        const ull* tw = reinterpret_cast<const ull*>(relW + (qw - j + 13) * 64);
        ull a0 = 0, a1 = 0, b0 = 0, b1 = 0;
#pragma unroll
        for (int d = 0; d < 32; d += 2) {
            ffma2(a0, q2[d],     th[d]);
            ffma2(a1, q2[d + 1], th[d + 1]);
            ffma2(b0, q2[d],     tw[d]);
            ffma2(b1, q2[d + 1], tw[d + 1]);
        }
        float2 ha = unpk(add2(a0, a1));
        float2 wa = unpk(add2(b0, b1));
        rh_s[j * 256 + tid] = ha.x + ha.y;
        rw_s[j * 256 + tid] = wa.x + wa.y;
    }

    float m = -1e30f, l = 0.0f;
    ull o2[32];
#pragma unroll
    for (int d = 0; d < 32; d++) o2[d] = 0ULL;

    int k = 0;
    for (int kh = 0; kh < 14; kh++) {
        float rhv = rh_s[kh * 256 + tid];
        for (int kw = 0; kw < 14; kw++, k++) {
            const ull* kp = reinterpret_cast<const ull*>(Ks + k * 64);
            ull s0 = 0, s1 = 0, s2 = 0, s3 = 0;
#pragma unroll
            for (int d = 0; d < 32; d += 4) {
                ffma2(s0, q2[d],     kp[d]);
                ffma2(s1, q2[d + 1], kp[d + 1]);
                ffma2(s2, q2[d + 2], kp[d + 2]);
                ffma2(s3, q2[d + 3], kp[d + 3]);
            }
            s0 = add2(s0, s1); s2 = add2(s2, s3); s0 = add2(s0, s2);
            float2 sp = unpk(s0);
            float s = fmaf(sp.x + sp.y, 0.125f, rhv + rw_s[kw * 256 + tid]);
            float p;
            if (s > m) {
                float corr = __expf(m - s);
                l *= corr;
                ull c2 = dup2(corr);
#pragma unroll
                for (int d = 0; d < 32; d++) o2[d] = mul2(o2[d], c2);
                m = s;
                p = 1.0f;
            } else {
                p = __expf(s - m);
            }
            l += p;
            ull p2 = dup2(p);
            const ull* vp = reinterpret_cast<const ull*>(Vs + k * 64);
#pragma unroll
            for (int d = 0; d < 32; d++) ffma2(o2[d], p2, vp[d]);
        }
    }
    ull iv = dup2(1.0f / l);
    float* op = out + (size_t)tok * CD + n * 64;
#pragma unroll
    for (int d = 0; d < 32; d++)
        *reinterpret_cast<ull*>(op + 2 * d) = mul2(o2[d], iv);
}

// ---------------------------------------------------------------------------
// Neck 3x3 conv, SAME, NHWC, HWIO, 256->256
// ---------------------------------------------------------------------------
__global__ __launch_bounds__(256) void conv3x3_kernel(
    const float* __restrict__ in, const float* __restrict__ w,
    float* __restrict__ out)
{
    __shared__ float patch[3 * 6 * 256];
    const int y = blockIdx.x >> 4;
    const int x0 = (blockIdx.x & 15) * 4;
    const int tid = threadIdx.x;

    for (int idx = tid; idx < 3 * 6 * 256; idx += 256) {
        int ci = idx & 255;
        int pos = idx >> 8;
        int dy = pos / 6, dx = pos % 6;
        int yy = y + dy - 1, xx = x0 + dx - 1;
        float v = 0.0f;
        if (yy >= 0 && yy < 64 && xx >= 0 && xx < 64)
            v = in[((size_t)(yy * 64 + xx)) * 256 + ci];
        patch[idx] = v;
    }
    __syncthreads();

    const int co = tid;
    float acc0 = 0.f, acc1 = 0.f, acc2 = 0.f, acc3 = 0.f;
#pragma unroll
    for (int dy = 0; dy < 3; dy++) {
#pragma unroll
        for (int dx = 0; dx < 3; dx++) {
            const float* wp = w + ((size_t)(dy * 3 + dx) * 256) * 256 + co;
            const float* pp = patch + (dy * 6 + dx) * 256;
#pragma unroll 4
            for (int ci = 0; ci < 256; ci++) {
                float wv = wp[(size_t)ci * 256];
                acc0 = fmaf(pp[ci], wv, acc0);
                acc1 = fmaf(pp[ci + 256], wv, acc1);
                acc2 = fmaf(pp[ci + 512], wv, acc2);
                acc3 = fmaf(pp[ci + 768], wv, acc3);
            }
        }
    }
    out[((size_t)(y * 64 + x0 + 0)) * 256 + co] = acc0;
    out[((size_t)(y * 64 + x0 + 1)) * 256 + co] = acc1;
    out[((size_t)(y * 64 + x0 + 2)) * 256 + co] = acc2;
    out[((size_t)(y * 64 + x0 + 3)) * 256 + co] = acc3;
}

// ---------------------------------------------------------------------------
// Launch
// ---------------------------------------------------------------------------
extern "C" void kernel_launch(void* const* d_in, const int* in_sizes, int n_in,
                              void* d_out, int out_size)
{
    (void)in_sizes; (void)n_in; (void)out_size;
    const float* x      = (const float*)d_in[0];
    const float* ln1_g  = (const float*)d_in[1];
    const float* ln1_b  = (const float*)d_in[2];
    const float* qkv_w  = (const float*)d_in[3];
    const float* qkv_b  = (const float*)d_in[4];
    const float* proj_w = (const float*)d_in[5];
    const float* proj_b = (const float*)d_in[6];
    const float* rel_h  = (const float*)d_in[7];
    const float* rel_w  = (const float*)d_in[8];
    const float* ln2_g  = (const float*)d_in[9];
    const float* ln2_b  = (const float*)d_in[10];
    const float* fc1_w  = (const float*)d_in[11];
    const float* fc1_b  = (const float*)d_in[12];
    const float* fc2_w  = (const float*)d_in[13];
    const float* fc2_b  = (const float*)d_in[14];
    const float* nc1    = (const float*)d_in[15];
    const float* nl1g   = (const float*)d_in[16];
    const float* nl1b   = (const float*)d_in[17];
    const float* nc2    = (const float*)d_in[18];
    const float* nl2g   = (const float*)d_in[19];
    const float* nl2b   = (const float*)d_in[20];
    float* out = (float*)d_out;

    float *gx, *gxn, *gqkv, *gattn, *gh, *gt1, *gt2, *gbh, *gbw;
    cudaGetSymbolAddress((void**)&gx,   g_x);
    cudaGetSymbolAddress((void**)&gxn,  g_xn);
    cudaGetSymbolAddress((void**)&gqkv, g_qkv);
    cudaGetSymbolAddress((void**)&gattn,g_attn);
    cudaGetSymbolAddress((void**)&gh,   g_h);
    cudaGetSymbolAddress((void**)&gt1,  g_t1);
    cudaGetSymbolAddress((void**)&gt2,  g_t2);
    cudaGetSymbolAddress((void**)&gbh,  g_bh);
    cudaGetSymbolAddress((void**)&gbw,  g_bw);

    cudaFuncSetAttribute(win_attn2_kernel,
                         cudaFuncAttributeMaxDynamicSharedMemorySize, WIN2_SMEM);
    cudaFuncSetAttribute(glob_attn2_kernel,
                         cudaFuncAttributeMaxDynamicSharedMemorySize, GA2_SMEM);
    cudaFuncSetAttribute(gemm3_kernel<false, true, false>,
                         cudaFuncAttributeMaxDynamicSharedMemorySize, G3_SMEM);
    cudaFuncSetAttribute(gemm3_kernel<false, true, true>,
                         cudaFuncAttributeMaxDynamicSharedMemorySize, G3_SMEM);
    cudaFuncSetAttribute(gemm3_kernel<true, true, false>,
                         cudaFuncAttributeMaxDynamicSharedMemorySize, G3_SMEM);
    cudaFuncSetAttribute(gemm3_kernel<false, false, false>,
                         cudaFuncAttributeMaxDynamicSharedMemorySize, G3_SMEM);

    cudaMemcpyAsync(gx, x, (size_t)TOK * CD * sizeof(float),
                    cudaMemcpyDeviceToDevice, 0);

    for (int b = 0; b < 4; b++) {
        ln768_kernel<<<TOK, 256>>>(gx, ln1_g + b * CD, ln1_b + b * CD, gxn, 1e-5f);
        gemm3_kernel<false, true, false><<<dim3(18, 32), 256, G3_SMEM>>>(
            gxn, qkv_w + (size_t)b * CD * 3 * CD, qkv_b + (size_t)b * 3 * CD,
            nullptr, gqkv, TOK, 3 * CD, CD);
        if (b < 3) {
            win_attn2_kernel<<<dim3(25, 12), 256, WIN2_SMEM>>>(
                gqkv, qkv_b + (size_t)b * 3 * CD,
                rel_h + (size_t)b * 127 * 64, rel_w + (size_t)b * 127 * 64, gattn);
        } else {
            relbias_kernel<<<dim3(TOK, 12), 64>>>(
                gqkv, rel_h + (size_t)b * 127 * 64, rel_w + (size_t)b * 127 * 64,
                gbh, gbw);
            glob_attn2_kernel<<<dim3(32, 12), 128, GA2_SMEM>>>(gqkv, gbh, gbw, gattn);
        }
        gemm3_kernel<false, true, true><<<dim3(6, 32), 256, G3_SMEM>>>(
            gattn, proj_w + (size_t)b * CD * CD, proj_b + (size_t)b * CD,
            gx, gx, TOK, CD, CD);
        ln768_kernel<<<TOK, 256>>>(gx, ln2_g + b * CD, ln2_b + b * CD, gxn, 1e-5f);
        gemm3_kernel<true, true, false><<<dim3(24, 32), 256, G3_SMEM>>>(
            gxn, fc1_w + (size_t)b * CD * FD, fc1_b + (size_t)b * FD,
            nullptr, gh, TOK, FD, CD);
        gemm3_kernel<false, true, true><<<dim3(6, 32), 256, G3_SMEM>>>(
            gh, fc2_w + (size_t)b * FD * CD, fc2_b + (size_t)b * CD,
            gx, gx, TOK, CD, FD);
    }

    gemm3_kernel<false, false, false><<<dim3(2, 32), 256, G3_SMEM>>>(
        gx, nc1, nullptr, nullptr, gt1, TOK, 256, CD);
    ln256_kernel<<<TOK, 256>>>(gt1, nl1g, nl1b, gt2, 1e-6f, 0);
    conv3x3_kernel<<<1024, 256>>>(gt2, nc2, gt1);
    ln256_kernel<<<TOK, 256>>>(gt1, nl2g, nl2b, out, 1e-6f, 1);
}

// round 8
// speedup vs baseline: 1.1203x; 1.1203x over previous
#include <cuda_runtime.h>
#include <cuda_bf16.h>
#include <math.h>
#include <stdint.h>

typedef unsigned long long ull;

// ---------------------------------------------------------------------------
// helpers
// ---------------------------------------------------------------------------
__device__ __forceinline__ void ffma2(ull& d, ull a, ull b) {
    asm("fma.rn.f32x2 %0, %1, %2, %0;" : "+l"(d) : "l"(a), "l"(b));
}
__device__ __forceinline__ ull add2(ull a, ull b) {
    ull r; asm("add.rn.f32x2 %0, %1, %2;" : "=l"(r) : "l"(a), "l"(b)); return r;
}
__device__ __forceinline__ ull mul2(ull a, ull b) {
    ull r; asm("mul.rn.f32x2 %0, %1, %2;" : "=l"(r) : "l"(a), "l"(b)); return r;
}
__device__ __forceinline__ ull dup2(float x) {
    ull r; asm("mov.b64 %0, {%1, %1};" : "=l"(r) : "f"(x)); return r;
}
__device__ __forceinline__ float2 unpk(ull v) {
    float2 r; asm("mov.b64 {%0, %1}, %2;" : "=f"(r.x), "=f"(r.y) : "l"(v)); return r;
}
__device__ __forceinline__ void mma_bf16(float* c, const uint32_t* a, const uint32_t* b) {
    asm volatile(
        "mma.sync.aligned.m16n8k16.row.col.f32.bf16.bf16.f32 "
        "{%0,%1,%2,%3}, {%4,%5,%6,%7}, {%8,%9}, {%0,%1,%2,%3};"
        : "+f"(c[0]), "+f"(c[1]), "+f"(c[2]), "+f"(c[3])
        : "r"(a[0]), "r"(a[1]), "r"(a[2]), "r"(a[3]), "r"(b[0]), "r"(b[1]));
}
// split (x,y) into bf16x2 hi word + bf16x2 lo word (lo = residual)
__device__ __forceinline__ void packhl(float x, float y, uint32_t& h, uint32_t& l) {
    __nv_bfloat162 hb = __floats2bfloat162_rn(x, y);   // .x = x (low half)
    h = *reinterpret_cast<uint32_t*>(&hb);
    float xr = __uint_as_float(h << 16);
    float yr = __uint_as_float(h & 0xFFFF0000u);
    __nv_bfloat162 lb = __floats2bfloat162_rn(x - xr, y - yr);
    l = *reinterpret_cast<uint32_t*>(&lb);
}

#define TOK 4096
#define CD 768
#define FD 3072

// weight word-buffer offsets (words = element pairs)
#define QW  884736
#define PW  294912
#define F1W 1179648
#define F2W 1179648
#define BSW (QW + PW + F1W + F2W)
#define NC1W 98304
#define TOTW (4 * BSW + NC1W)

__device__ float g_x[TOK * CD];
__device__ float g_qkv[TOK * 3 * CD];
__device__ float g_t1[TOK * 256];
__device__ float g_t2[TOK * 256];
__device__ float g_bh[12 * TOK * 64];
__device__ float g_bw[12 * TOK * 64];
__device__ uint32_t g_wh[TOTW];
__device__ uint32_t g_wl[TOTW];
__device__ uint32_t g_ah[TOK * 384];
__device__ uint32_t g_al[TOK * 384];
__device__ uint32_t g_hh[TOK * 1536];
__device__ uint32_t g_hl[TOK * 1536];

// ---------------------------------------------------------------------------
// weight conversion: f32 [2*Kw][N] -> word arrays [Kw][N], word = {W[2kp][n],W[2kp+1][n]}
// ---------------------------------------------------------------------------
__global__ __launch_bounds__(256) void cvt_rowpair(
    const float* __restrict__ W, uint32_t* __restrict__ Wh, uint32_t* __restrict__ Wl,
    int Kw, int N)
{
    int idx = blockIdx.x * 256 + threadIdx.x;
    if (idx >= Kw * N) return;
    int kp = idx / N, n = idx - kp * N;
    float x = W[(size_t)(2 * kp) * N + n];
    float y = W[(size_t)(2 * kp + 1) * N + n];
    uint32_t h, l;
    packhl(x, y, h, l);
    Wh[idx] = h; Wl[idx] = l;
}

// activation conversion: f32 row-major, pairs along columns (contiguous)
__global__ __launch_bounds__(256) void cvt_colpair(
    const float* __restrict__ A, uint32_t* __restrict__ Ah, uint32_t* __restrict__ Al,
    int total)
{
    int idx = blockIdx.x * 256 + threadIdx.x;
    if (idx >= total) return;
    float2 f = reinterpret_cast<const float2*>(A)[idx];
    uint32_t h, l;
    packhl(f.x, f.y, h, l);
    Ah[idx] = h; Al[idx] = l;
}

// ---------------------------------------------------------------------------
// LayerNorm 768 -> bf16 hi/lo word output. 128 threads, 6 channels each.
// ---------------------------------------------------------------------------
__global__ __launch_bounds__(128) void ln768b_kernel(
    const float* __restrict__ in, const float* __restrict__ g,
    const float* __restrict__ b, uint32_t* __restrict__ oh, uint32_t* __restrict__ ol,
    float eps)
{
    int row = blockIdx.x;
    int t = threadIdx.x;
    const float* xp = in + (size_t)row * CD + 6 * t;
    float2 a0 = *reinterpret_cast<const float2*>(xp);
    float2 a1 = *reinterpret_cast<const float2*>(xp + 2);
    float2 a2 = *reinterpret_cast<const float2*>(xp + 4);
    __shared__ float red[128];
    red[t] = a0.x + a0.y + a1.x + a1.y + a2.x + a2.y;
    __syncthreads();
#pragma unroll
    for (int off = 64; off > 0; off >>= 1) {
        if (t < off) red[t] += red[t + off];
        __syncthreads();
    }
    float mean = red[0] * (1.0f / 768.0f);
    __syncthreads();
    float d0 = a0.x - mean, d1 = a0.y - mean, d2 = a1.x - mean;
    float d3 = a1.y - mean, d4 = a2.x - mean, d5 = a2.y - mean;
    red[t] = d0 * d0 + d1 * d1 + d2 * d2 + d3 * d3 + d4 * d4 + d5 * d5;
    __syncthreads();
#pragma unroll
    for (int off = 64; off > 0; off >>= 1) {
        if (t < off) red[t] += red[t + off];
        __syncthreads();
    }
    float inv = rsqrtf(red[0] * (1.0f / 768.0f) + eps);
    const float* gp = g + 6 * t;
    const float* bp = b + 6 * t;
    float y0 = d0 * inv * gp[0] + bp[0];
    float y1 = d1 * inv * gp[1] + bp[1];
    float y2 = d2 * inv * gp[2] + bp[2];
    float y3 = d3 * inv * gp[3] + bp[3];
    float y4 = d4 * inv * gp[4] + bp[4];
    float y5 = d5 * inv * gp[5] + bp[5];
    size_t base = (size_t)row * 384 + 3 * t;
    uint32_t h, l;
    packhl(y0, y1, h, l); oh[base] = h;     ol[base] = l;
    packhl(y2, y3, h, l); oh[base + 1] = h; ol[base + 1] = l;
    packhl(y4, y5, h, l); oh[base + 2] = h; ol[base + 2] = l;
}

// ---------------------------------------------------------------------------
// LayerNorm 256 (neck), optional NCHW transpose
// ---------------------------------------------------------------------------
__global__ __launch_bounds__(256) void ln256_kernel(
    const float* __restrict__ in, const float* __restrict__ g,
    const float* __restrict__ b, float* __restrict__ out, float eps, int transpose)
{
    int p = blockIdx.x;
    int c = threadIdx.x;
    float v = in[(size_t)p * 256 + c];
    __shared__ float red[256];
    red[c] = v;
    __syncthreads();
#pragma unroll
    for (int off = 128; off > 0; off >>= 1) {
        if (c < off) red[c] += red[c + off];
        __syncthreads();
    }
    float mean = red[0] * (1.0f / 256.0f);
    __syncthreads();
    float d = v - mean;
    red[c] = d * d;
    __syncthreads();
#pragma unroll
    for (int off = 128; off > 0; off >>= 1) {
        if (c < off) red[c] += red[c + off];
        __syncthreads();
    }
    float inv = rsqrtf(red[0] * (1.0f / 256.0f) + eps);
    float r = d * inv * g[c] + b[c];
    if (transpose)
        out[(size_t)c * TOK + p] = r;
    else
        out[(size_t)p * 256 + c] = r;
}

// ---------------------------------------------------------------------------
// GEMM v4: bf16 tensor core, 3xBF16 (hi*hi + lo*hi + hi*lo).
// Inputs pre-split into bf16x2 word arrays: A [M][Kw], B [Kw][N] (k-paired).
// Block 128x128x32, 8 warps (2x4), warp 64x32, mma m16n8k16.
// A smem: [128][24] words, in-row perm w'=2(p&3)+((p>>2)&1)+8(p>>3) so
//   {a0,a2} and {a1,a3} frags are single LDS.64s; stride 24 -> conflict-free.
// B smem: [16][128] words, swizzle n^((kp&3)<<3) -> conflict-free LDS.32.
// ---------------------------------------------------------------------------
template<bool GELU, bool HASBIAS, bool HASRES, bool OUTBF>
__global__ __launch_bounds__(256) void gemm4_kernel(
    const uint32_t* __restrict__ Ah, const uint32_t* __restrict__ Al,
    const uint32_t* __restrict__ Bh, const uint32_t* __restrict__ Bl,
    const float* __restrict__ bias, const float* __restrict__ res,
    float* __restrict__ Cf, uint32_t* __restrict__ Ch, uint32_t* __restrict__ Cl,
    int M, int N, int K)
{
    __shared__ __align__(16) uint32_t Ahs[128 * 24];
    __shared__ __align__(16) uint32_t Als[128 * 24];
    __shared__ __align__(16) uint32_t Bhs[16 * 128];
    __shared__ __align__(16) uint32_t Bls[16 * 128];

    const int tid = threadIdx.x;
    const int lane = tid & 31;
    const int warp = tid >> 5;
    const int wm = (warp >> 2) * 64;
    const int wn = (warp & 3) * 32;
    const int r = lane >> 2;
    const int cc = lane & 3;
    const int row0 = blockIdx.y * 128, col0 = blockIdx.x * 128;
    const int Kw = K >> 1;

    float acc[4][4][4];
#pragma unroll
    for (int mi = 0; mi < 4; mi++)
#pragma unroll
        for (int ni = 0; ni < 4; ni++)
#pragma unroll
            for (int j = 0; j < 4; j++) acc[mi][ni][j] = 0.0f;

    const int am = tid >> 1;          // 0..127
    const int aj = tid & 1;           // word group 8*aj
    const int bkp = tid >> 4;         // 0..15
    const int bn4 = (tid & 15) * 4;

    uint4 pah[2], pal[2], pbh[2], pbl[2];

#define LOADG(T) do { \
        size_t ab = (size_t)(row0 + am) * Kw + (T) * 16 + 8 * aj; \
        pah[0] = *reinterpret_cast<const uint4*>(Ah + ab); \
        pah[1] = *reinterpret_cast<const uint4*>(Ah + ab + 4); \
        pal[0] = *reinterpret_cast<const uint4*>(Al + ab); \
        pal[1] = *reinterpret_cast<const uint4*>(Al + ab + 4); \
        size_t bb = (size_t)((T) * 16 + bkp) * N + col0 + bn4; \
        pbh[0] = *reinterpret_cast<const uint4*>(Bh + bb); \
        pbh[1] = *reinterpret_cast<const uint4*>(Bh + bb + 64); \
        pbl[0] = *reinterpret_cast<const uint4*>(Bl + bb); \
        pbl[1] = *reinterpret_cast<const uint4*>(Bl + bb + 64); \
    } while (0)

#define STORES() do { \
        int abase = am * 24 + 8 * aj; \
        *reinterpret_cast<uint4*>(Ahs + abase) = \
            make_uint4(pah[0].x, pah[1].x, pah[0].y, pah[1].y); \
        *reinterpret_cast<uint4*>(Ahs + abase + 4) = \
            make_uint4(pah[0].z, pah[1].z, pah[0].w, pah[1].w); \
        *reinterpret_cast<uint4*>(Als + abase) = \
            make_uint4(pal[0].x, pal[1].x, pal[0].y, pal[1].y); \
        *reinterpret_cast<uint4*>(Als + abase + 4) = \
            make_uint4(pal[0].z, pal[1].z, pal[0].w, pal[1].w); \
        int sw = (bkp & 3) << 3; \
        int b0 = bkp * 128 + (bn4 ^ sw); \
        int b1 = bkp * 128 + ((bn4 + 64) ^ sw); \
        *reinterpret_cast<uint4*>(Bhs + b0) = pbh[0]; \
        *reinterpret_cast<uint4*>(Bhs + b1) = pbh[1]; \
        *reinterpret_cast<uint4*>(Bls + b0) = pbl[0]; \
        *reinterpret_cast<uint4*>(Bls + b1) = pbl[1]; \
    } while (0)

    const int NT = K >> 5;
    LOADG(0);

    for (int t = 0; t < NT; t++) {
        STORES();
        __syncthreads();
        if (t + 1 < NT) LOADG(t + 1);

#pragma unroll
        for (int ks = 0; ks < 2; ks++) {
            uint32_t fah[4][4], fal[4][4], fbh[4][2], fbl[4][2];
#pragma unroll
            for (int mi = 0; mi < 4; mi++) {
                int m0 = wm + mi * 16 + r;
                int off = 2 * cc + 8 * ks;
                ull t0 = *reinterpret_cast<const ull*>(Ahs + m0 * 24 + off);
                ull t1 = *reinterpret_cast<const ull*>(Ahs + (m0 + 8) * 24 + off);
                fah[mi][0] = (uint32_t)t0; fah[mi][2] = (uint32_t)(t0 >> 32);
                fah[mi][1] = (uint32_t)t1; fah[mi][3] = (uint32_t)(t1 >> 32);
                ull u0 = *reinterpret_cast<const ull*>(Als + m0 * 24 + off);
                ull u1 = *reinterpret_cast<const ull*>(Als + (m0 + 8) * 24 + off);
                fal[mi][0] = (uint32_t)u0; fal[mi][2] = (uint32_t)(u0 >> 32);
                fal[mi][1] = (uint32_t)u1; fal[mi][3] = (uint32_t)(u1 >> 32);
            }
#pragma unroll
            for (int ni = 0; ni < 4; ni++) {
                int n = wn + ni * 8 + r;
                int ns = n ^ (cc << 3);
                int kp0 = (cc + 8 * ks) * 128;
                int kp1 = (cc + 4 + 8 * ks) * 128;
                fbh[ni][0] = Bhs[kp0 + ns];
                fbh[ni][1] = Bhs[kp1 + ns];
                fbl[ni][0] = Bls[kp0 + ns];
                fbl[ni][1] = Bls[kp1 + ns];
            }
#pragma unroll
            for (int mi = 0; mi < 4; mi++)
#pragma unroll
                for (int ni = 0; ni < 4; ni++) {
                    mma_bf16(acc[mi][ni], fah[mi], fbh[ni]);
                    mma_bf16(acc[mi][ni], fal[mi], fbh[ni]);
                    mma_bf16(acc[mi][ni], fah[mi], fbl[ni]);
                }
        }
        __syncthreads();
    }
#undef LOADG
#undef STORES

    // epilogue: frag c0,c1 -> (row, 2cc),(row, 2cc+1); c2,c3 -> row+8
#pragma unroll
    for (int mi = 0; mi < 4; mi++) {
#pragma unroll
        for (int half = 0; half < 2; half++) {
            int grow = row0 + wm + mi * 16 + r + half * 8;
#pragma unroll
            for (int ni = 0; ni < 4; ni++) {
                int gcol = col0 + wn + ni * 8 + 2 * cc;
                float v0 = acc[mi][ni][half * 2 + 0];
                float v1 = acc[mi][ni][half * 2 + 1];
                if (HASBIAS) { v0 += bias[gcol]; v1 += bias[gcol + 1]; }
                if (GELU) {
                    v0 = 0.5f * v0 * (1.0f + erff(v0 * 0.70710678118654752f));
                    v1 = 0.5f * v1 * (1.0f + erff(v1 * 0.70710678118654752f));
                }
                if (OUTBF) {
                    uint32_t h, l;
                    packhl(v0, v1, h, l);
                    size_t o = (size_t)grow * (N >> 1) + (gcol >> 1);
                    Ch[o] = h; Cl[o] = l;
                } else {
                    size_t o = (size_t)grow * N + gcol;
                    if (HASRES) {
                        float2 rr = *reinterpret_cast<const float2*>(res + o);
                        v0 += rr.x; v1 += rr.y;
                    }
                    *reinterpret_cast<float2*>(Cf + o) = make_float2(v0, v1);
                }
            }
        }
    }
}

// ---------------------------------------------------------------------------
// Rel-pos bias precompute (global attention block)
// ---------------------------------------------------------------------------
__global__ __launch_bounds__(64) void relbias_kernel(
    const float* __restrict__ qkv, const float* __restrict__ relH,
    const float* __restrict__ relW, float* __restrict__ bh, float* __restrict__ bw)
{
    int q = blockIdx.x, n = blockIdx.y, j = threadIdx.x;
    __shared__ float qs[64];
    qs[j] = qkv[(size_t)q * 2304 + n * 64 + j];
    __syncthreads();
    int qh = q >> 6, qw = q & 63;
    const float* th = relH + (qh - j + 63) * 64;
    const float* tw = relW + (qw - j + 63) * 64;
    float a = 0.f, b = 0.f;
#pragma unroll 8
    for (int d = 0; d < 64; d++) {
        a = fmaf(qs[d], th[d], a);
        b = fmaf(qs[d], tw[d], b);
    }
    size_t o = ((size_t)n * TOK + q) * 64 + j;
    bh[o] = a;
    bw[o] = b;
}

// ---------------------------------------------------------------------------
// Global attention: 128 queries/block, f32x2 math; writes bf16 hi/lo words.
// ---------------------------------------------------------------------------
#define GA2_SMEM ((128 * 65 * 2 + 64 * 64 * 2) * 4)

__global__ __launch_bounds__(128) void glob_attn2_kernel(
    const float* __restrict__ qkv, const float* __restrict__ bh,
    const float* __restrict__ bw, uint32_t* __restrict__ oh, uint32_t* __restrict__ ol)
{
    extern __shared__ float sm[];
    float* rh_s = sm;
    float* rw_s = sm + 128 * 65;
    float* Ks   = sm + 2 * 128 * 65;
    float* Vs   = Ks + 64 * 64;
    const int n = blockIdx.y, tid = threadIdx.x;
    const int q0 = blockIdx.x * 128;

    for (int idx = tid; idx < 128 * 64; idx += 128) {
        int qq = idx >> 6, j = idx & 63;
        size_t g = ((size_t)n * TOK + q0 + qq) * 64 + j;
        rh_s[qq * 65 + j] = bh[g];
        rw_s[qq * 65 + j] = bw[g];
    }

    ull q2[32], o2[32];
    const float* qp = qkv + (size_t)(q0 + tid) * 2304 + n * 64;
#pragma unroll
    for (int i = 0; i < 32; i++) {
        q2[i] = *reinterpret_cast<const ull*>(qp + 2 * i);
        o2[i] = 0ULL;
    }
    float m = -1e30f, l = 0.0f;

    for (int kt = 0; kt < 64; kt++) {
        __syncthreads();
#pragma unroll
        for (int i = 0; i < 8; i++) {
            int idx = tid + i * 128;
            int row = idx >> 4, c4 = (idx & 15) * 4;
            const float* kb = qkv + (size_t)(kt * 64 + row) * 2304 + 768 + n * 64 + c4;
            *reinterpret_cast<float4*>(&Ks[row * 64 + c4]) = *reinterpret_cast<const float4*>(kb);
            *reinterpret_cast<float4*>(&Vs[row * 64 + c4]) = *reinterpret_cast<const float4*>(kb + 768);
        }
        __syncthreads();
        float rhv = rh_s[tid * 65 + kt];
        for (int kk = 0; kk < 64; kk++) {
            const ull* kp = reinterpret_cast<const ull*>(Ks + kk * 64);
            ull s0 = 0, s1 = 0, s2 = 0, s3 = 0;
#pragma unroll
            for (int d = 0; d < 32; d += 4) {
                ffma2(s0, q2[d],     kp[d]);
                ffma2(s1, q2[d + 1], kp[d + 1]);
                ffma2(s2, q2[d + 2], kp[d + 2]);
                ffma2(s3, q2[d + 3], kp[d + 3]);
            }
            s0 = add2(s0, s1); s2 = add2(s2, s3); s0 = add2(s0, s2);
            float2 sp = unpk(s0);
            float s = fmaf(sp.x + sp.y, 0.125f, rhv + rw_s[tid * 65 + kk]);
            float p;
            if (s > m) {
                float corr = __expf(m - s);
                l *= corr;
                ull c2 = dup2(corr);
#pragma unroll
                for (int d = 0; d < 32; d++) o2[d] = mul2(o2[d], c2);
                m = s;
                p = 1.0f;
            } else {
                p = __expf(s - m);
            }
            l += p;
            ull p2 = dup2(p);
            const ull* vp = reinterpret_cast<const ull*>(Vs + kk * 64);
#pragma unroll
            for (int d = 0; d < 32; d++) ffma2(o2[d], p2, vp[d]);
        }
    }
    ull iv = dup2(1.0f / l);
    size_t base = (size_t)(q0 + tid) * 384 + n * 32;
#pragma unroll
    for (int d = 0; d < 32; d++) {
        float2 ov = unpk(mul2(o2[d], iv));
        uint32_t h, lw;
        packhl(ov.x, ov.y, h, lw);
        oh[base + d] = h;
        ol[base + d] = lw;
    }
}

// ---------------------------------------------------------------------------
// Windowed attention (ws=14): f32x2 math; writes bf16 hi/lo words.
// ---------------------------------------------------------------------------
#define WIN2_SMEM ((196 * 64 * 2 + 2 * 14 * 256) * 4)

__global__ __launch_bounds__(256) void win_attn2_kernel(
    const float* __restrict__ qkv, const float* __restrict__ qkv_b,
    const float* __restrict__ relH, const float* __restrict__ relW,
    uint32_t* __restrict__ oh, uint32_t* __restrict__ ol)
{
    extern __shared__ float sm[];
    float* Ks = sm;
    float* Vs = sm + 196 * 64;
    float* rh_s = sm + 2 * 196 * 64;
    float* rw_s = rh_s + 14 * 256;
    const int win = blockIdx.x, n = blockIdx.y;
    const int wh = (win / 5) * 14, ww = (win % 5) * 14;
    const int tid = threadIdx.x;

    for (int idx = tid; idx < 196 * 64; idx += 256) {
        int rr = idx >> 6, d = idx & 63;
        int gh = wh + rr / 14, gw = ww + rr % 14;
        float kk, vv;
        if (gh < 64 && gw < 64) {
            size_t base = (size_t)(gh * 64 + gw) * 2304 + n * 64 + d;
            kk = qkv[base + 768];
            vv = qkv[base + 1536];
        } else {
            kk = qkv_b[768 + n * 64 + d];
            vv = qkv_b[1536 + n * 64 + d];
        }
        Ks[idx] = kk;
        Vs[idx] = vv;
    }
    __syncthreads();

    if (tid >= 196) return;
    const int qh = tid / 14, qw = tid % 14;
    const int gh = wh + qh, gw = ww + qw;
    if (gh >= 64 || gw >= 64) return;
    const int tok = gh * 64 + gw;

    ull q2[32];
    const float* qp = qkv + (size_t)tok * 2304 + n * 64;
#pragma unroll
    for (int i = 0; i < 32; i++) q2[i] = *reinterpret_cast<const ull*>(qp + 2 * i);

#pragma unroll 2
    for (int j = 0; j < 14; j++) {
        const ull* th = reinterpret_cast<const ull*>(relH + (qh - j + 13) * 64);
        const ull* tw = reinterpret_cast<const ull*>(relW + (qw - j + 13) * 64);
        ull a0 = 0, a1 = 0, b0 = 0, b1 = 0;
#pragma unroll
        for (int d = 0; d < 32; d += 2) {
            ffma2(a0, q2[d],     th[d]);
            ffma2(a1, q2[d + 1], th[d + 1]);
            ffma2(b0, q2[d],     tw[d]);
            ffma2(b1, q2[d + 1], tw[d + 1]);
        }
        float2 ha = unpk(add2(a0, a1));
        float2 wa = unpk(add2(b0, b1));
        rh_s[j * 256 + tid] = ha.x + ha.y;
        rw_s[j * 256 + tid] = wa.x + wa.y;
    }

    float m = -1e30f, l = 0.0f;
    ull o2[32];
#pragma unroll
    for (int d = 0; d < 32; d++) o2[d] = 0ULL;

    int k = 0;
    for (int kh = 0; kh < 14; kh++) {
        float rhv = rh_s[kh * 256 + tid];
        for (int kw = 0; kw < 14; kw++, k++) {
            const ull* kp = reinterpret_cast<const ull*>(Ks + k * 64);
            ull s0 = 0, s1 = 0, s2 = 0, s3 = 0;
#pragma unroll
            for (int d = 0; d < 32; d += 4) {
                ffma2(s0, q2[d],     kp[d]);
                ffma2(s1, q2[d + 1], kp[d + 1]);
                ffma2(s2, q2[d + 2], kp[d + 2]);
                ffma2(s3, q2[d + 3], kp[d + 3]);
            }
            s0 = add2(s0, s1); s2 = add2(s2, s3); s0 = add2(s0, s2);
            float2 sp = unpk(s0);
            float s = fmaf(sp.x + sp.y, 0.125f, rhv + rw_s[kw * 256 + tid]);
            float p;
            if (s > m) {
                float corr = __expf(m - s);
                l *= corr;
                ull c2 = dup2(corr);
#pragma unroll
                for (int d = 0; d < 32; d++) o2[d] = mul2(o2[d], c2);
                m = s;
                p = 1.0f;
            } else {
                p = __expf(s - m);
            }
            l += p;
            ull p2 = dup2(p);
            const ull* vp = reinterpret_cast<const ull*>(Vs + k * 64);
#pragma unroll
            for (int d = 0; d < 32; d++) ffma2(o2[d], p2, vp[d]);
        }
    }
    ull iv = dup2(1.0f / l);
    size_t base = (size_t)tok * 384 + n * 32;
#pragma unroll
    for (int d = 0; d < 32; d++) {
        float2 ov = unpk(mul2(o2[d], iv));
        uint32_t h, lw;
        packhl(ov.x, ov.y, h, lw);
        oh[base + d] = h;
        ol[base + d] = lw;
    }
}

// ---------------------------------------------------------------------------
// Neck 3x3 conv, SAME, NHWC, HWIO, 256->256
// ---------------------------------------------------------------------------
__global__ __launch_bounds__(256) void conv3x3_kernel(
    const float* __restrict__ in, const float* __restrict__ w,
    float* __restrict__ out)
{
    __shared__ float patch[3 * 6 * 256];
    const int y = blockIdx.x >> 4;
    const int x0 = (blockIdx.x & 15) * 4;
    const int tid = threadIdx.x;

    for (int idx = tid; idx < 3 * 6 * 256; idx += 256) {
        int ci = idx & 255;
        int pos = idx >> 8;
        int dy = pos / 6, dx = pos % 6;
        int yy = y + dy - 1, xx = x0 + dx - 1;
        float v = 0.0f;
        if (yy >= 0 && yy < 64 && xx >= 0 && xx < 64)
            v = in[((size_t)(yy * 64 + xx)) * 256 + ci];
        patch[idx] = v;
    }
    __syncthreads();

    const int co = tid;
    float acc0 = 0.f, acc1 = 0.f, acc2 = 0.f, acc3 = 0.f;
#pragma unroll
    for (int dy = 0; dy < 3; dy++) {
#pragma unroll
        for (int dx = 0; dx < 3; dx++) {
            const float* wp = w + ((size_t)(dy * 3 + dx) * 256) * 256 + co;
            const float* pp = patch + (dy * 6 + dx) * 256;
#pragma unroll 4
            for (int ci = 0; ci < 256; ci++) {
                float wv = wp[(size_t)ci * 256];
                acc0 = fmaf(pp[ci], wv, acc0);
                acc1 = fmaf(pp[ci + 256], wv, acc1);
                acc2 = fmaf(pp[ci + 512], wv, acc2);
                acc3 = fmaf(pp[ci + 768], wv, acc3);
            }
        }
    }
    out[((size_t)(y * 64 + x0 + 0)) * 256 + co] = acc0;
    out[((size_t)(y * 64 + x0 + 1)) * 256 + co] = acc1;
    out[((size_t)(y * 64 + x0 + 2)) * 256 + co] = acc2;
    out[((size_t)(y * 64 + x0 + 3)) * 256 + co] = acc3;
}

// ---------------------------------------------------------------------------
// Launch
// ---------------------------------------------------------------------------
extern "C" void kernel_launch(void* const* d_in, const int* in_sizes, int n_in,
                              void* d_out, int out_size)
{
    (void)in_sizes; (void)n_in; (void)out_size;
    const float* x      = (const float*)d_in[0];
    const float* ln1_g  = (const float*)d_in[1];
    const float* ln1_b  = (const float*)d_in[2];
    const float* qkv_w  = (const float*)d_in[3];
    const float* qkv_b  = (const float*)d_in[4];
    const float* proj_w = (const float*)d_in[5];
    const float* proj_b = (const float*)d_in[6];
    const float* rel_h  = (const float*)d_in[7];
    const float* rel_w  = (const float*)d_in[8];
    const float* ln2_g  = (const float*)d_in[9];
    const float* ln2_b  = (const float*)d_in[10];
    const float* fc1_w  = (const float*)d_in[11];
    const float* fc1_b  = (const float*)d_in[12];
    const float* fc2_w  = (const float*)d_in[13];
    const float* fc2_b  = (const float*)d_in[14];
    const float* nc1    = (const float*)d_in[15];
    const float* nl1g   = (const float*)d_in[16];
    const float* nl1b   = (const float*)d_in[17];
    const float* nc2    = (const float*)d_in[18];
    const float* nl2g   = (const float*)d_in[19];
    const float* nl2b   = (const float*)d_in[20];
    float* out = (float*)d_out;

    float *gx, *gqkv, *gt1, *gt2, *gbh, *gbw;
    uint32_t *gwh, *gwl, *gah, *gal, *ghh, *ghl;
    cudaGetSymbolAddress((void**)&gx,   g_x);
    cudaGetSymbolAddress((void**)&gqkv, g_qkv);
    cudaGetSymbolAddress((void**)&gt1,  g_t1);
    cudaGetSymbolAddress((void**)&gt2,  g_t2);
    cudaGetSymbolAddress((void**)&gbh,  g_bh);
    cudaGetSymbolAddress((void**)&gbw,  g_bw);
    cudaGetSymbolAddress((void**)&gwh,  g_wh);
    cudaGetSymbolAddress((void**)&gwl,  g_wl);
    cudaGetSymbolAddress((void**)&gah,  g_ah);
    cudaGetSymbolAddress((void**)&gal,  g_al);
    cudaGetSymbolAddress((void**)&ghh,  g_hh);
    cudaGetSymbolAddress((void**)&ghl,  g_hl);

    cudaFuncSetAttribute(win_attn2_kernel,
                         cudaFuncAttributeMaxDynamicSharedMemorySize, WIN2_SMEM);
    cudaFuncSetAttribute(glob_attn2_kernel,
                         cudaFuncAttributeMaxDynamicSharedMemorySize, GA2_SMEM);

    cudaMemcpyAsync(gx, x, (size_t)TOK * CD * sizeof(float),
                    cudaMemcpyDeviceToDevice, 0);

    // weight conversion (per-launch, deterministic)
    for (int b = 0; b < 4; b++) {
        size_t o = (size_t)b * BSW;
        cvt_rowpair<<<(384 * 2304 + 255) / 256, 256>>>(
            qkv_w + (size_t)b * CD * 3 * CD, gwh + o, gwl + o, 384, 2304);
        cvt_rowpair<<<(384 * 768 + 255) / 256, 256>>>(
            proj_w + (size_t)b * CD * CD, gwh + o + QW, gwl + o + QW, 384, 768);
        cvt_rowpair<<<(384 * 3072 + 255) / 256, 256>>>(
            fc1_w + (size_t)b * CD * FD, gwh + o + QW + PW, gwl + o + QW + PW, 384, 3072);
        cvt_rowpair<<<(1536 * 768 + 255) / 256, 256>>>(
            fc2_w + (size_t)b * FD * CD, gwh + o + QW + PW + F1W, gwl + o + QW + PW + F1W,
            1536, 768);
    }
    cvt_rowpair<<<(384 * 256 + 255) / 256, 256>>>(
        nc1, gwh + 4 * (size_t)BSW, gwl + 4 * (size_t)BSW, 384, 256);

    for (int b = 0; b < 4; b++) {
        size_t o = (size_t)b * BSW;
        ln768b_kernel<<<TOK, 128>>>(gx, ln1_g + b * CD, ln1_b + b * CD, gah, gal, 1e-5f);
        gemm4_kernel<false, true, false, false><<<dim3(18, 32), 256>>>(
            gah, gal, gwh + o, gwl + o, qkv_b + (size_t)b * 3 * CD, nullptr,
            gqkv, nullptr, nullptr, TOK, 2304, 768);
        if (b < 3) {
            win_attn2_kernel<<<dim3(25, 12), 256, WIN2_SMEM>>>(
                gqkv, qkv_b + (size_t)b * 3 * CD,
                rel_h + (size_t)b * 127 * 64, rel_w + (size_t)b * 127 * 64, gah, gal);
        } else {
            relbias_kernel<<<dim3(TOK, 12), 64>>>(
                gqkv, rel_h + (size_t)b * 127 * 64, rel_w + (size_t)b * 127 * 64,
                gbh, gbw);
            glob_attn2_kernel<<<dim3(32, 12), 128, GA2_SMEM>>>(gqkv, gbh, gbw, gah, gal);
        }
        gemm4_kernel<false, true, true, false><<<dim3(6, 32), 256>>>(
            gah, gal, gwh + o + QW, gwl + o + QW, proj_b + (size_t)b * CD, gx,
            gx, nullptr, nullptr, TOK, 768, 768);
        ln768b_kernel<<<TOK, 128>>>(gx, ln2_g + b * CD, ln2_b + b * CD, gah, gal, 1e-5f);
        gemm4_kernel<true, true, false, true><<<dim3(24, 32), 256>>>(
            gah, gal, gwh + o + QW + PW, gwl + o + QW + PW, fc1_b + (size_t)b * FD, nullptr,
            nullptr, ghh, ghl, TOK, 3072, 768);
        gemm4_kernel<false, true, true, false><<<dim3(6, 32), 256>>>(
            ghh, ghl, gwh + o + QW + PW + F1W, gwl + o + QW + PW + F1W,
            fc2_b + (size_t)b * CD, gx, gx, nullptr, nullptr, TOK, 768, 3072);
    }

    // neck
    cvt_colpair<<<(TOK * 384 + 255) / 256, 256>>>(gx, gah, gal, TOK * 384);
    gemm4_kernel<false, false, false, false><<<dim3(2, 32), 256>>>(
        gah, gal, gwh + 4 * (size_t)BSW, gwl + 4 * (size_t)BSW, nullptr, nullptr,
        gt1, nullptr, nullptr, TOK, 256, 768);
    ln256_kernel<<<TOK, 256>>>(gt1, nl1g, nl1b, gt2, 1e-6f, 0);
    conv3x3_kernel<<<1024, 256>>>(gt2, nc2, gt1);
    ln256_kernel<<<TOK, 256>>>(gt1, nl2g, nl2b, out, 1e-6f, 1);
}

// round 13
// speedup vs baseline: 1.2595x; 1.1242x over previous
#include <cuda_runtime.h>
#include <cuda_fp16.h>
#include <math.h>
#include <stdint.h>

typedef unsigned long long ull;

// ---------------------------------------------------------------------------
// scalar helpers
// ---------------------------------------------------------------------------
__device__ __forceinline__ void ffma2(ull& d, ull a, ull b) {
    asm("fma.rn.f32x2 %0, %1, %2, %0;" : "+l"(d) : "l"(a), "l"(b));
}
__device__ __forceinline__ ull add2(ull a, ull b) {
    ull r; asm("add.rn.f32x2 %0, %1, %2;" : "=l"(r) : "l"(a), "l"(b)); return r;
}
__device__ __forceinline__ ull mul2(ull a, ull b) {
    ull r; asm("mul.rn.f32x2 %0, %1, %2;" : "=l"(r) : "l"(a), "l"(b)); return r;
}
__device__ __forceinline__ ull dup2(float x) {
    ull r; asm("mov.b64 %0, {%1, %1};" : "=l"(r) : "f"(x)); return r;
}
__device__ __forceinline__ float2 unpk(ull v) {
    float2 r; asm("mov.b64 {%0, %1}, %2;" : "=f"(r.x), "=f"(r.y) : "l"(v)); return r;
}
// fp16 packing: hi word (fp16x2) + lo residual word (fp16x2)
__device__ __forceinline__ void packhl16(float x, float y, uint32_t& h, uint32_t& l) {
    __half2 hb = __floats2half2_rn(x, y);
    h = *reinterpret_cast<uint32_t*>(&hb);
    float2 hr = __half22float2(hb);
    __half2 lb = __floats2half2_rn(x - hr.x, y - hr.y);
    l = *reinterpret_cast<uint32_t*>(&lb);
}
__device__ __forceinline__ uint32_t pack16(float x, float y) {
    __half2 hb = __floats2half2_rn(x, y);
    return *reinterpret_cast<uint32_t*>(&hb);
}
__device__ __forceinline__ void mma_f16(float* c, const uint32_t* a, const uint32_t* b) {
    asm volatile(
        "mma.sync.aligned.m16n8k16.row.col.f32.f16.f16.f32 "
        "{%0,%1,%2,%3}, {%4,%5,%6,%7}, {%8,%9}, {%0,%1,%2,%3};"
        : "+f"(c[0]), "+f"(c[1]), "+f"(c[2]), "+f"(c[3])
        : "r"(a[0]), "r"(a[1]), "r"(a[2]), "r"(a[3]), "r"(b[0]), "r"(b[1]));
}

#define TOK 4096
#define CD 768
#define FD 3072

// weight word-buffer offsets (words = k-pair element pairs)
#define QW  884736
#define PW  294912
#define F1W 1179648
#define F2W 1179648
#define BSW (QW + PW + F1W + F2W)
#define NC1W 98304
#define TOTW (4 * BSW + NC1W)

__device__ float g_x[TOK * CD];
__device__ float g_qkv[TOK * 3 * CD];
__device__ float g_t1[TOK * 256];
__device__ float g_t2[TOK * 256];
__device__ float g_bh[12 * TOK * 64];
__device__ float g_bw[12 * TOK * 64];
__device__ uint32_t g_wh[TOTW];
__device__ uint32_t g_ah[TOK * 384];
__device__ uint32_t g_al[TOK * 384];
__device__ uint32_t g_hh[TOK * 1536];
__device__ uint32_t g_hl[TOK * 1536];

// ---------------------------------------------------------------------------
// input copy (own launch -> stable ncu launch indexing)
// ---------------------------------------------------------------------------
__global__ __launch_bounds__(256) void copy_kernel(
    const float4* __restrict__ in, float4* __restrict__ out, int n)
{
    int i = blockIdx.x * 256 + threadIdx.x;
    if (i < n) out[i] = in[i];
}

// ---------------------------------------------------------------------------
// weight convert: f32 W[2*Kw][N] -> fp16x2 word [Kw][N], word={W[2kp][n],W[2kp+1][n]}
// ---------------------------------------------------------------------------
__global__ __launch_bounds__(256) void cvt_w16(
    const float* __restrict__ W, uint32_t* __restrict__ Wh, int Kw, int N)
{
    int idx = blockIdx.x * 256 + threadIdx.x;
    if (idx >= Kw * N) return;
    int kp = idx / N, n = idx - kp * N;
    Wh[idx] = pack16(W[(size_t)(2 * kp) * N + n], W[(size_t)(2 * kp + 1) * N + n]);
}

// activation conversion: f32 row-major, pairs along columns (contiguous)
__global__ __launch_bounds__(256) void cvt_colpair(
    const float* __restrict__ A, uint32_t* __restrict__ Ah, uint32_t* __restrict__ Al,
    int total)
{
    int idx = blockIdx.x * 256 + threadIdx.x;
    if (idx >= total) return;
    float2 f = reinterpret_cast<const float2*>(A)[idx];
    uint32_t h, l;
    packhl16(f.x, f.y, h, l);
    Ah[idx] = h; Al[idx] = l;
}

// ---------------------------------------------------------------------------
// LayerNorm 768 -> fp16 hi/lo words
// ---------------------------------------------------------------------------
__global__ __launch_bounds__(128) void ln768b_kernel(
    const float* __restrict__ in, const float* __restrict__ g,
    const float* __restrict__ b, uint32_t* __restrict__ oh, uint32_t* __restrict__ ol,
    float eps)
{
    int row = blockIdx.x;
    int t = threadIdx.x;
    const float* xp = in + (size_t)row * CD + 6 * t;
    float2 a0 = *reinterpret_cast<const float2*>(xp);
    float2 a1 = *reinterpret_cast<const float2*>(xp + 2);
    float2 a2 = *reinterpret_cast<const float2*>(xp + 4);
    __shared__ float red[128];
    red[t] = a0.x + a0.y + a1.x + a1.y + a2.x + a2.y;
    __syncthreads();
#pragma unroll
    for (int off = 64; off > 0; off >>= 1) {
        if (t < off) red[t] += red[t + off];
        __syncthreads();
    }
    float mean = red[0] * (1.0f / 768.0f);
    __syncthreads();
    float d0 = a0.x - mean, d1 = a0.y - mean, d2 = a1.x - mean;
    float d3 = a1.y - mean, d4 = a2.x - mean, d5 = a2.y - mean;
    red[t] = d0 * d0 + d1 * d1 + d2 * d2 + d3 * d3 + d4 * d4 + d5 * d5;
    __syncthreads();
#pragma unroll
    for (int off = 64; off > 0; off >>= 1) {
        if (t < off) red[t] += red[t + off];
        __syncthreads();
    }
    float inv = rsqrtf(red[0] * (1.0f / 768.0f) + eps);
    const float* gp = g + 6 * t;
    const float* bp = b + 6 * t;
    float y0 = d0 * inv * gp[0] + bp[0];
    float y1 = d1 * inv * gp[1] + bp[1];
    float y2 = d2 * inv * gp[2] + bp[2];
    float y3 = d3 * inv * gp[3] + bp[3];
    float y4 = d4 * inv * gp[4] + bp[4];
    float y5 = d5 * inv * gp[5] + bp[5];
    size_t base = (size_t)row * 384 + 3 * t;
    uint32_t h, l;
    packhl16(y0, y1, h, l); oh[base] = h;     ol[base] = l;
    packhl16(y2, y3, h, l); oh[base + 1] = h; ol[base + 1] = l;
    packhl16(y4, y5, h, l); oh[base + 2] = h; ol[base + 2] = l;
}

// ---------------------------------------------------------------------------
// LayerNorm 256 (neck), optional NCHW transpose
// ---------------------------------------------------------------------------
__global__ __launch_bounds__(256) void ln256_kernel(
    const float* __restrict__ in, const float* __restrict__ g,
    const float* __restrict__ b, float* __restrict__ out, float eps, int transpose)
{
    int p = blockIdx.x;
    int c = threadIdx.x;
    float v = in[(size_t)p * 256 + c];
    __shared__ float red[256];
    red[c] = v;
    __syncthreads();
#pragma unroll
    for (int off = 128; off > 0; off >>= 1) {
        if (c < off) red[c] += red[c + off];
        __syncthreads();
    }
    float mean = red[0] * (1.0f / 256.0f);
    __syncthreads();
    float d = v - mean;
    red[c] = d * d;
    __syncthreads();
#pragma unroll
    for (int off = 128; off > 0; off >>= 1) {
        if (c < off) red[c] += red[c + off];
        __syncthreads();
    }
    float inv = rsqrtf(red[0] * (1.0f / 256.0f) + eps);
    float r = d * inv * g[c] + b[c];
    if (transpose)
        out[(size_t)c * TOK + p] = r;
    else
        out[(size_t)p * 256 + c] = r;
}

// ---------------------------------------------------------------------------
// GEMM v6: fp16 tensor core, 2-pass (A = hi+lo fp16 = 22 bits, B = fp16 hi).
// A [M][Kw] words, B [Kw][N] words (k-paired). Block 128x128x32, 8 warps,
// warp 64x32, mma m16n8k16. Double-buffered smem, ONE sync per k-tile.
// A smem: [128][24-stride] words, in-row permute so frags are LDS.64.
// B smem: [16][128] words, swizzle n^((kp&3)<<3).
// ---------------------------------------------------------------------------
#define G6_STAGEW 8192
#define G6_ALW 3072
#define G6_BHW 6144
#define G6_SMEM (2 * G6_STAGEW * 4)

template<bool GELU, bool HASBIAS, bool HASRES, bool OUTHL>
__global__ __launch_bounds__(256) void gemm6_kernel(
    const uint32_t* __restrict__ Ah, const uint32_t* __restrict__ Al,
    const uint32_t* __restrict__ Bh,
    const float* __restrict__ bias, const float* __restrict__ res,
    float* __restrict__ Cf, uint32_t* __restrict__ Ch, uint32_t* __restrict__ Cl,
    int M, int N, int K)
{
    extern __shared__ uint32_t smw[];
    const int tid = threadIdx.x;
    const int lane = tid & 31;
    const int warp = tid >> 5;
    const int wm = (warp >> 2) * 64;
    const int wn = (warp & 3) * 32;
    const int r = lane >> 2;
    const int cc = lane & 3;
    const int row0 = blockIdx.y * 128, col0 = blockIdx.x * 128;
    const int Kw = K >> 1;

    float acc[4][4][4];
#pragma unroll
    for (int mi = 0; mi < 4; mi++)
#pragma unroll
        for (int ni = 0; ni < 4; ni++)
#pragma unroll
            for (int j = 0; j < 4; j++) acc[mi][ni][j] = 0.0f;

    const int am = tid >> 1;          // 0..127
    const int aj = tid & 1;           // word group 8*aj
    const int bkp = tid >> 4;         // 0..15
    const int bn4 = (tid & 15) * 4;

    uint4 pah[2], pal[2], pbh[2];

#define LOADG(T) do { \
        size_t ab = (size_t)(row0 + am) * Kw + (T) * 16 + 8 * aj; \
        pah[0] = *reinterpret_cast<const uint4*>(Ah + ab); \
        pah[1] = *reinterpret_cast<const uint4*>(Ah + ab + 4); \
        pal[0] = *reinterpret_cast<const uint4*>(Al + ab); \
        pal[1] = *reinterpret_cast<const uint4*>(Al + ab + 4); \
        size_t bb = (size_t)((T) * 16 + bkp) * N + col0 + bn4; \
        pbh[0] = *reinterpret_cast<const uint4*>(Bh + bb); \
        pbh[1] = *reinterpret_cast<const uint4*>(Bh + bb + 64); \
    } while (0)

#define STORES(BUF) do { \
        uint32_t* dst = smw + (BUF) * G6_STAGEW; \
        int abase = am * 24 + 8 * aj; \
        *reinterpret_cast<uint4*>(dst + abase) = \
            make_uint4(pah[0].x, pah[1].x, pah[0].y, pah[1].y); \
        *reinterpret_cast<uint4*>(dst + abase + 4) = \
            make_uint4(pah[0].z, pah[1].z, pah[0].w, pah[1].w); \
        *reinterpret_cast<uint4*>(dst + G6_ALW + abase) = \
            make_uint4(pal[0].x, pal[1].x, pal[0].y, pal[1].y); \
        *reinterpret_cast<uint4*>(dst + G6_ALW + abase + 4) = \
            make_uint4(pal[0].z, pal[1].z, pal[0].w, pal[1].w); \
        int sw = (bkp & 3) << 3; \
        *reinterpret_cast<uint4*>(dst + G6_BHW + bkp * 128 + (bn4 ^ sw)) = pbh[0]; \
        *reinterpret_cast<uint4*>(dst + G6_BHW + bkp * 128 + ((bn4 + 64) ^ sw)) = pbh[1]; \
    } while (0)

    const int NT = K >> 5;
    LOADG(0);
    STORES(0);
    __syncthreads();

    for (int t = 0; t < NT; t++) {
        if (t + 1 < NT) LOADG(t + 1);
        const uint32_t* Ahs = smw + (t & 1) * G6_STAGEW;
        const uint32_t* Als = Ahs + G6_ALW;
        const uint32_t* Bhs = Ahs + G6_BHW;
#pragma unroll
        for (int ks = 0; ks < 2; ks++) {
            uint32_t fah[4][4], fal[4][4], fbh[4][2];
#pragma unroll
            for (int mi = 0; mi < 4; mi++) {
                int m0 = wm + mi * 16 + r;
                int off = 2 * cc + 8 * ks;
                ull t0 = *reinterpret_cast<const ull*>(Ahs + m0 * 24 + off);
                ull t1 = *reinterpret_cast<const ull*>(Ahs + (m0 + 8) * 24 + off);
                fah[mi][0] = (uint32_t)t0; fah[mi][2] = (uint32_t)(t0 >> 32);
                fah[mi][1] = (uint32_t)t1; fah[mi][3] = (uint32_t)(t1 >> 32);
                ull u0 = *reinterpret_cast<const ull*>(Als + m0 * 24 + off);
                ull u1 = *reinterpret_cast<const ull*>(Als + (m0 + 8) * 24 + off);
                fal[mi][0] = (uint32_t)u0; fal[mi][2] = (uint32_t)(u0 >> 32);
                fal[mi][1] = (uint32_t)u1; fal[mi][3] = (uint32_t)(u1 >> 32);
            }
#pragma unroll
            for (int ni = 0; ni < 4; ni++) {
                int n = wn + ni * 8 + r;
                int ns = n ^ (cc << 3);
                fbh[ni][0] = Bhs[(cc + 8 * ks) * 128 + ns];
                fbh[ni][1] = Bhs[(cc + 4 + 8 * ks) * 128 + ns];
            }
#pragma unroll
            for (int mi = 0; mi < 4; mi++)
#pragma unroll
                for (int ni = 0; ni < 4; ni++) {
                    mma_f16(acc[mi][ni], fah[mi], fbh[ni]);
                    mma_f16(acc[mi][ni], fal[mi], fbh[ni]);
                }
        }
        if (t + 1 < NT) STORES((t + 1) & 1);
        __syncthreads();
    }
#undef LOADG
#undef STORES

    // epilogue: frag c0,c1 -> (row, 2cc),(row, 2cc+1); c2,c3 -> row+8
#pragma unroll
    for (int mi = 0; mi < 4; mi++) {
#pragma unroll
        for (int half = 0; half < 2; half++) {
            int grow = row0 + wm + mi * 16 + r + half * 8;
#pragma unroll
            for (int ni = 0; ni < 4; ni++) {
                int gcol = col0 + wn + ni * 8 + 2 * cc;
                float v0 = acc[mi][ni][half * 2 + 0];
                float v1 = acc[mi][ni][half * 2 + 1];
                if (HASBIAS) { v0 += bias[gcol]; v1 += bias[gcol + 1]; }
                if (GELU) {
                    v0 = 0.5f * v0 * (1.0f + erff(v0 * 0.70710678118654752f));
                    v1 = 0.5f * v1 * (1.0f + erff(v1 * 0.70710678118654752f));
                }
                if (OUTHL) {
                    uint32_t h, l;
                    packhl16(v0, v1, h, l);
                    size_t o = (size_t)grow * (N >> 1) + (gcol >> 1);
                    Ch[o] = h; Cl[o] = l;
                } else {
                    size_t o = (size_t)grow * N + gcol;
                    if (HASRES) {
                        float2 rr = *reinterpret_cast<const float2*>(res + o);
                        v0 += rr.x; v1 += rr.y;
                    }
                    *reinterpret_cast<float2*>(Cf + o) = make_float2(v0, v1);
                }
            }
        }
    }
}

// ---------------------------------------------------------------------------
// Rel-pos bias precompute (global attention block)
// ---------------------------------------------------------------------------
__global__ __launch_bounds__(64) void relbias_kernel(
    const float* __restrict__ qkv, const float* __restrict__ relH,
    const float* __restrict__ relW, float* __restrict__ bh, float* __restrict__ bw)
{
    int q = blockIdx.x, n = blockIdx.y, j = threadIdx.x;
    __shared__ float qs[64];
    qs[j] = qkv[(size_t)q * 2304 + n * 64 + j];
    __syncthreads();
    int qh = q >> 6, qw = q & 63;
    const float* th = relH + (qh - j + 63) * 64;
    const float* tw = relW + (qw - j + 63) * 64;
    float a = 0.f, b = 0.f;
#pragma unroll 8
    for (int d = 0; d < 64; d++) {
        a = fmaf(qs[d], th[d], a);
        b = fmaf(qs[d], tw[d], b);
    }
    size_t o = ((size_t)n * TOK + q) * 64 + j;
    bh[o] = a;
    bw[o] = b;
}

// ---------------------------------------------------------------------------
// Global attention: 128 queries/block, f32x2 math; writes fp16 hi/lo words.
// ---------------------------------------------------------------------------
#define GA2_SMEM ((128 * 65 * 2 + 64 * 64 * 2) * 4)

__global__ __launch_bounds__(128) void glob_attn2_kernel(
    const float* __restrict__ qkv, const float* __restrict__ bh,
    const float* __restrict__ bw, uint32_t* __restrict__ oh, uint32_t* __restrict__ ol)
{
    extern __shared__ float sm[];
    float* rh_s = sm;
    float* rw_s = sm + 128 * 65;
    float* Ks   = sm + 2 * 128 * 65;
    float* Vs   = Ks + 64 * 64;
    const int n = blockIdx.y, tid = threadIdx.x;
    const int q0 = blockIdx.x * 128;

    for (int idx = tid; idx < 128 * 64; idx += 128) {
        int qq = idx >> 6, j = idx & 63;
        size_t g = ((size_t)n * TOK + q0 + qq) * 64 + j;
        rh_s[qq * 65 + j] = bh[g];
        rw_s[qq * 65 + j] = bw[g];
    }

    ull q2[32], o2[32];
    const float* qp = qkv + (size_t)(q0 + tid) * 2304 + n * 64;
#pragma unroll
    for (int i = 0; i < 32; i++) {
        q2[i] = *reinterpret_cast<const ull*>(qp + 2 * i);
        o2[i] = 0ULL;
    }
    float m = -1e30f, l = 0.0f;

    for (int kt = 0; kt < 64; kt++) {
        __syncthreads();
#pragma unroll
        for (int i = 0; i < 8; i++) {
            int idx = tid + i * 128;
            int row = idx >> 4, c4 = (idx & 15) * 4;
            const float* kb = qkv + (size_t)(kt * 64 + row) * 2304 + 768 + n * 64 + c4;
            *reinterpret_cast<float4*>(&Ks[row * 64 + c4]) = *reinterpret_cast<const float4*>(kb);
            *reinterpret_cast<float4*>(&Vs[row * 64 + c4]) = *reinterpret_cast<const float4*>(kb + 768);
        }
        __syncthreads();
        float rhv = rh_s[tid * 65 + kt];
        for (int kk = 0; kk < 64; kk++) {
            const ull* kp = reinterpret_cast<const ull*>(Ks + kk * 64);
            ull s0 = 0, s1 = 0, s2 = 0, s3 = 0;
#pragma unroll
            for (int d = 0; d < 32; d += 4) {
                ffma2(s0, q2[d],     kp[d]);
                ffma2(s1, q2[d + 1], kp[d + 1]);
                ffma2(s2, q2[d + 2], kp[d + 2]);
                ffma2(s3, q2[d + 3], kp[d + 3]);
            }
            s0 = add2(s0, s1); s2 = add2(s2, s3); s0 = add2(s0, s2);
            float2 sp = unpk(s0);
            float s = fmaf(sp.x + sp.y, 0.125f, rhv + rw_s[tid * 65 + kk]);
            float p;
            if (s > m) {
                float corr = __expf(m - s);
                l *= corr;
                ull c2 = dup2(corr);
#pragma unroll
                for (int d = 0; d < 32; d++) o2[d] = mul2(o2[d], c2);
                m = s;
                p = 1.0f;
            } else {
                p = __expf(s - m);
            }
            l += p;
            ull p2 = dup2(p);
            const ull* vp = reinterpret_cast<const ull*>(Vs + kk * 64);
#pragma unroll
            for (int d = 0; d < 32; d++) ffma2(o2[d], p2, vp[d]);
        }
    }
    ull iv = dup2(1.0f / l);
    size_t base = (size_t)(q0 + tid) * 384 + n * 32;
#pragma unroll
    for (int d = 0; d < 32; d++) {
        float2 ov = unpk(mul2(o2[d], iv));
        uint32_t h, lw;
        packhl16(ov.x, ov.y, h, lw);
        oh[base + d] = h;
        ol[base + d] = lw;
    }
}

// ---------------------------------------------------------------------------
// Windowed attention (ws=14); writes fp16 hi/lo words.
// ---------------------------------------------------------------------------
#define WIN2_SMEM ((196 * 64 * 2 + 2 * 14 * 256) * 4)

__global__ __launch_bounds__(256) void win_attn2_kernel(
    const float* __restrict__ qkv, const float* __restrict__ qkv_b,
    const float* __restrict__ relH, const float* __restrict__ relW,
    uint32_t* __restrict__ oh, uint32_t* __restrict__ ol)
{
    extern __shared__ float sm[];
    float* Ks = sm;
    float* Vs = sm + 196 * 64;
    float* rh_s = sm + 2 * 196 * 64;
    float* rw_s = rh_s + 14 * 256;
    const int win = blockIdx.x, n = blockIdx.y;
    const int wh = (win / 5) * 14, ww = (win % 5) * 14;
    const int tid = threadIdx.x;

    for (int idx = tid; idx < 196 * 64; idx += 256) {
        int rr = idx >> 6, d = idx & 63;
        int gh = wh + rr / 14, gw = ww + rr % 14;
        float kk, vv;
        if (gh < 64 && gw < 64) {
            size_t base = (size_t)(gh * 64 + gw) * 2304 + n * 64 + d;
            kk = qkv[base + 768];
            vv = qkv[base + 1536];
        } else {
            kk = qkv_b[768 + n * 64 + d];
            vv = qkv_b[1536 + n * 64 + d];
        }
        Ks[idx] = kk;
        Vs[idx] = vv;
    }
    __syncthreads();

    if (tid >= 196) return;
    const int qh = tid / 14, qw = tid % 14;
    const int gh = wh + qh, gw = ww + qw;
    if (gh >= 64 || gw >= 64) return;
    const int tok = gh * 64 + gw;

    ull q2[32];
    const float* qp = qkv + (size_t)tok * 2304 + n * 64;
#pragma unroll
    for (int i = 0; i < 32; i++) q2[i] = *reinterpret_cast<const ull*>(qp + 2 * i);

#pragma unroll 2
    for (int j = 0; j < 14; j++) {
        const ull* th = reinterpret_cast<const ull*>(relH + (qh - j + 13) * 64);
        const ull* tw = reinterpret_cast<const ull*>(relW + (qw - j + 13) * 64);
        ull a0 = 0, a1 = 0, b0 = 0, b1 = 0;
#pragma unroll
        for (int d = 0; d < 32; d += 2) {
            ffma2(a0, q2[d],     th[d]);
            ffma2(a1, q2[d + 1], th[d + 1]);
            ffma2(b0, q2[d],     tw[d]);
            ffma2(b1, q2[d + 1], tw[d + 1]);
        }
        float2 ha = unpk(add2(a0, a1));
        float2 wa = unpk(add2(b0, b1));
        rh_s[j * 256 + tid] = ha.x + ha.y;
        rw_s[j * 256 + tid] = wa.x + wa.y;
    }

    float m = -1e30f, l = 0.0f;
    ull o2[32];
#pragma unroll
    for (int d = 0; d < 32; d++) o2[d] = 0ULL;

    int k = 0;
    for (int kh = 0; kh < 14; kh++) {
        float rhv = rh_s[kh * 256 + tid];
        for (int kw = 0; kw < 14; kw++, k++) {
            const ull* kp = reinterpret_cast<const ull*>(Ks + k * 64);
            ull s0 = 0, s1 = 0, s2 = 0, s3 = 0;
#pragma unroll
            for (int d = 0; d < 32; d += 4) {
                ffma2(s0, q2[d],     kp[d]);
                ffma2(s1, q2[d + 1], kp[d + 1]);
                ffma2(s2, q2[d + 2], kp[d + 2]);
                ffma2(s3, q2[d + 3], kp[d + 3]);
            }
            s0 = add2(s0, s1); s2 = add2(s2, s3); s0 = add2(s0, s2);
            float2 sp = unpk(s0);
            float s = fmaf(sp.x + sp.y, 0.125f, rhv + rw_s[kw * 256 + tid]);
            float p;
            if (s > m) {
                float corr = __expf(m - s);
                l *= corr;
                ull c2 = dup2(corr);
#pragma unroll
                for (int d = 0; d < 32; d++) o2[d] = mul2(o2[d], c2);
                m = s;
                p = 1.0f;
            } else {
                p = __expf(s - m);
            }
            l += p;
            ull p2 = dup2(p);
            const ull* vp = reinterpret_cast<const ull*>(Vs + k * 64);
#pragma unroll
            for (int d = 0; d < 32; d++) ffma2(o2[d], p2, vp[d]);
        }
    }
    ull iv = dup2(1.0f / l);
    size_t base = (size_t)tok * 384 + n * 32;
#pragma unroll
    for (int d = 0; d < 32; d++) {
        float2 ov = unpk(mul2(o2[d], iv));
        uint32_t h, lw;
        packhl16(ov.x, ov.y, h, lw);
        oh[base + d] = h;
        ol[base + d] = lw;
    }
}

// ---------------------------------------------------------------------------
// Neck 3x3 conv, SAME, NHWC, HWIO, 256->256
// ---------------------------------------------------------------------------
__global__ __launch_bounds__(256) void conv3x3_kernel(
    const float* __restrict__ in, const float* __restrict__ w,
    float* __restrict__ out)
{
    __shared__ float patch[3 * 6 * 256];
    const int y = blockIdx.x >> 4;
    const int x0 = (blockIdx.x & 15) * 4;
    const int tid = threadIdx.x;

    for (int idx = tid; idx < 3 * 6 * 256; idx += 256) {
        int ci = idx & 255;
        int pos = idx >> 8;
        int dy = pos / 6, dx = pos % 6;
        int yy = y + dy - 1, xx = x0 + dx - 1;
        float v = 0.0f;
        if (yy >= 0 && yy < 64 && xx >= 0 && xx < 64)
            v = in[((size_t)(yy * 64 + xx)) * 256 + ci];
        patch[idx] = v;
    }
    __syncthreads();

    const int co = tid;
    float acc0 = 0.f, acc1 = 0.f, acc2 = 0.f, acc3 = 0.f;
#pragma unroll
    for (int dy = 0; dy < 3; dy++) {
#pragma unroll
        for (int dx = 0; dx < 3; dx++) {
            const float* wp = w + ((size_t)(dy * 3 + dx) * 256) * 256 + co;
            const float* pp = patch + (dy * 6 + dx) * 256;
#pragma unroll 4
            for (int ci = 0; ci < 256; ci++) {
                float wv = wp[(size_t)ci * 256];
                acc0 = fmaf(pp[ci], wv, acc0);
                acc1 = fmaf(pp[ci + 256], wv, acc1);
                acc2 = fmaf(pp[ci + 512], wv, acc2);
                acc3 = fmaf(pp[ci + 768], wv, acc3);
            }
        }
    }
    out[((size_t)(y * 64 + x0 + 0)) * 256 + co] = acc0;
    out[((size_t)(y * 64 + x0 + 1)) * 256 + co] = acc1;
    out[((size_t)(y * 64 + x0 + 2)) * 256 + co] = acc2;
    out[((size_t)(y * 64 + x0 + 3)) * 256 + co] = acc3;
}

// ---------------------------------------------------------------------------
// Launch
// ---------------------------------------------------------------------------
extern "C" void kernel_launch(void* const* d_in, const int* in_sizes, int n_in,
                              void* d_out, int out_size)
{
    (void)in_sizes; (void)n_in; (void)out_size;
    const float* x      = (const float*)d_in[0];
    const float* ln1_g  = (const float*)d_in[1];
    const float* ln1_b  = (const float*)d_in[2];
    const float* qkv_w  = (const float*)d_in[3];
    const float* qkv_b  = (const float*)d_in[4];
    const float* proj_w = (const float*)d_in[5];
    const float* proj_b = (const float*)d_in[6];
    const float* rel_h  = (const float*)d_in[7];
    const float* rel_w  = (const float*)d_in[8];
    const float* ln2_g  = (const float*)d_in[9];
    const float* ln2_b  = (const float*)d_in[10];
    const float* fc1_w  = (const float*)d_in[11];
    const float* fc1_b  = (const float*)d_in[12];
    const float* fc2_w  = (const float*)d_in[13];
    const float* fc2_b  = (const float*)d_in[14];
    const float* nc1    = (const float*)d_in[15];
    const float* nl1g   = (const float*)d_in[16];
    const float* nl1b   = (const float*)d_in[17];
    const float* nc2    = (const float*)d_in[18];
    const float* nl2g   = (const float*)d_in[19];
    const float* nl2b   = (const float*)d_in[20];
    float* out = (float*)d_out;

    float *gx, *gqkv, *gt1, *gt2, *gbh, *gbw;
    uint32_t *gwh, *gah, *gal, *ghh, *ghl;
    cudaGetSymbolAddress((void**)&gx,   g_x);
    cudaGetSymbolAddress((void**)&gqkv, g_qkv);
    cudaGetSymbolAddress((void**)&gt1,  g_t1);
    cudaGetSymbolAddress((void**)&gt2,  g_t2);
    cudaGetSymbolAddress((void**)&gbh,  g_bh);
    cudaGetSymbolAddress((void**)&gbw,  g_bw);
    cudaGetSymbolAddress((void**)&gwh,  g_wh);
    cudaGetSymbolAddress((void**)&gah,  g_ah);
    cudaGetSymbolAddress((void**)&gal,  g_al);
    cudaGetSymbolAddress((void**)&ghh,  g_hh);
    cudaGetSymbolAddress((void**)&ghl,  g_hl);

    cudaFuncSetAttribute(win_attn2_kernel,
                         cudaFuncAttributeMaxDynamicSharedMemorySize, WIN2_SMEM);
    cudaFuncSetAttribute(glob_attn2_kernel,
                         cudaFuncAttributeMaxDynamicSharedMemorySize, GA2_SMEM);
    cudaFuncSetAttribute(gemm6_kernel<false, true, false, false>,
                         cudaFuncAttributeMaxDynamicSharedMemorySize, G6_SMEM);
    cudaFuncSetAttribute(gemm6_kernel<false, true, true, false>,
                         cudaFuncAttributeMaxDynamicSharedMemorySize, G6_SMEM);
    cudaFuncSetAttribute(gemm6_kernel<true, true, false, true>,
                         cudaFuncAttributeMaxDynamicSharedMemorySize, G6_SMEM);
    cudaFuncSetAttribute(gemm6_kernel<false, false, false, false>,
                         cudaFuncAttributeMaxDynamicSharedMemorySize, G6_SMEM);

    // launch 1: input copy
    copy_kernel<<<3072, 256>>>((const float4*)x, (float4*)gx, TOK * CD / 4);

    for (int b = 0; b < 4; b++) {
        size_t o = (size_t)b * BSW;
        // ordering keeps the qkv gemm6 at launch #6 for ncu (-s 5 -c 1)
        cvt_w16<<<3456, 256>>>(qkv_w + (size_t)b * CD * 3 * CD, gwh + o, 384, 2304);
        ln768b_kernel<<<TOK, 128>>>(gx, ln1_g + b * CD, ln1_b + b * CD, gah, gal, 1e-5f);
        cvt_w16<<<1152, 256>>>(proj_w + (size_t)b * CD * CD, gwh + o + QW, 384, 768);
        cvt_w16<<<4608, 256>>>(fc1_w + (size_t)b * CD * FD, gwh + o + QW + PW, 384, 3072);
        gemm6_kernel<false, true, false, false><<<dim3(18, 32), 256, G6_SMEM>>>(
            gah, gal, gwh + o, qkv_b + (size_t)b * 3 * CD, nullptr,
            gqkv, nullptr, nullptr, TOK, 2304, 768);
        cvt_w16<<<4608, 256>>>(fc2_w + (size_t)b * FD * CD, gwh + o + QW + PW + F1W,
                               1536, 768);
        if (b < 3) {
            win_attn2_kernel<<<dim3(25, 12), 256, WIN2_SMEM>>>(
                gqkv, qkv_b + (size_t)b * 3 * CD,
                rel_h + (size_t)b * 127 * 64, rel_w + (size_t)b * 127 * 64, gah, gal);
        } else {
            relbias_kernel<<<dim3(TOK, 12), 64>>>(
                gqkv, rel_h + (size_t)b * 127 * 64, rel_w + (size_t)b * 127 * 64,
                gbh, gbw);
            glob_attn2_kernel<<<dim3(32, 12), 128, GA2_SMEM>>>(gqkv, gbh, gbw, gah, gal);
        }
        gemm6_kernel<false, true, true, false><<<dim3(6, 32), 256, G6_SMEM>>>(
            gah, gal, gwh + o + QW, proj_b + (size_t)b * CD, gx,
            gx, nullptr, nullptr, TOK, 768, 768);
        ln768b_kernel<<<TOK, 128>>>(gx, ln2_g + b * CD, ln2_b + b * CD, gah, gal, 1e-5f);
        gemm6_kernel<true, true, false, true><<<dim3(24, 32), 256, G6_SMEM>>>(
            gah, gal, gwh + o + QW + PW, fc1_b + (size_t)b * FD, nullptr,
            nullptr, ghh, ghl, TOK, 3072, 768);
        gemm6_kernel<false, true, true, false><<<dim3(6, 32), 256, G6_SMEM>>>(
            ghh, ghl, gwh + o + QW + PW + F1W, fc2_b + (size_t)b * CD, gx,
            gx, nullptr, nullptr, TOK, 768, 3072);
    }

    // neck
    cvt_w16<<<384, 256>>>(nc1, gwh + 4 * (size_t)BSW, 384, 256);
    cvt_colpair<<<(TOK * 384 + 255) / 256, 256>>>(gx, gah, gal, TOK * 384);
    gemm6_kernel<false, false, false, false><<<dim3(2, 32), 256, G6_SMEM>>>(
        gah, gal, gwh + 4 * (size_t)BSW, nullptr, nullptr,
        gt1, nullptr, nullptr, TOK, 256, 768);
    ln256_kernel<<<TOK, 256>>>(gt1, nl1g, nl1b, gt2, 1e-6f, 0);
    conv3x3_kernel<<<1024, 256>>>(gt2, nc2, gt1);
    ln256_kernel<<<TOK, 256>>>(gt1, nl2g, nl2b, out, 1e-6f, 1);
}